// round 15
// baseline (speedup 1.0000x reference)
#include <cuda_runtime.h>
#include <cuda_fp16.h>
#include <cstdint>

// ---------------- problem constants ----------------
#define BB 8
#define CC 256
#define DD 100
#define NN 64
#define HEADS 8
#define HDIM 32
#define O3 768
#define NTOT 6400      // D*N per batch

// ---------------- device scratch (referenced ONLY from device code) ----------------
__device__ __half g_xp  [BB*DD*100*CC];  // padded transposed input [b][d][p100][c]
__device__ __half g_xlt [BB*NTOT*CC];    // conv out transposed [b][n][c]
__device__ __half g_qkv [BB*O3*NTOT];    // qkv [b][o][ntot]
__device__ __half g_xat [BB*NTOT*CC];    // attn out transposed [b][n][c]
__device__ __half g_wconv[9*CC*CC];      // [k][o][c]
__device__ __half g_wqc [O3*CC];         // qkv_w
__device__ __half g_wpc [CC*CC];         // proj_w

// ---------------- helpers ----------------
typedef unsigned long long u64t;

__device__ __forceinline__ uint32_t smem_u32(const void* p) {
    uint32_t a;
    asm("{ .reg .u64 t; cvta.to.shared.u64 t, %1; cvt.u32.u64 %0, t; }" : "=r"(a) : "l"(p));
    return a;
}
__device__ __forceinline__ void cpasync16(uint32_t dst, const void* src) {
    asm volatile("cp.async.cg.shared.global [%0], [%1], 16;" :: "r"(dst), "l"(src) : "memory");
}
__device__ __forceinline__ void cp_commit() { asm volatile("cp.async.commit_group;" ::: "memory"); }
__device__ __forceinline__ void cp_wait1()  { asm volatile("cp.async.wait_group 1;" ::: "memory"); }
__device__ __forceinline__ void cp_wait0()  { asm volatile("cp.async.wait_group 0;" ::: "memory"); }

__device__ __forceinline__ u64t pk2(float lo, float hi) {
    u64t r; asm("mov.b64 %0,{%1,%2};" : "=l"(r) : "f"(lo), "f"(hi)); return r;
}
__device__ __forceinline__ void fma2(u64t& d, u64t a, u64t b) {
    asm("fma.rn.f32x2 %0,%1,%2,%0;" : "+l"(d) : "l"(a), "l"(b));
}
__device__ __forceinline__ void upk2(u64t v, float& lo, float& hi) {
    asm("mov.b64 {%0,%1},%2;" : "=f"(lo), "=f"(hi) : "l"(v));
}

__device__ __forceinline__ void mma_f16(float c[4], const uint32_t a[4], const uint32_t b[2]) {
    asm volatile(
        "mma.sync.aligned.m16n8k16.row.col.f32.f16.f16.f32 "
        "{%0,%1,%2,%3}, {%4,%5,%6,%7}, {%8,%9}, {%0,%1,%2,%3};"
        : "+f"(c[0]), "+f"(c[1]), "+f"(c[2]), "+f"(c[3])
        : "r"(a[0]), "r"(a[1]), "r"(a[2]), "r"(a[3]), "r"(b[0]), "r"(b[1]));
}
__device__ __forceinline__ void ldsm_x4(uint32_t& r0, uint32_t& r1, uint32_t& r2, uint32_t& r3,
                                        uint32_t addr) {
    asm volatile("ldmatrix.sync.aligned.m8n8.x4.shared.b16 {%0,%1,%2,%3}, [%4];"
                 : "=r"(r0), "=r"(r1), "=r"(r2), "=r"(r3) : "r"(addr));
}

// generic GEMM tiles: 128 rows x KC halves; row stride KC+8 halves
template<int KC> struct TC {
    static constexpr int STRH  = KC + 8;
    static constexpr int TFH   = 128 * STRH;
    static constexpr int SMEMB = 4 * TFH * 2;
};

// warp-tile MMA over one staged 128xKC half chunk pair; ldmatrix fragment loads
template<int KC>
__device__ __forceinline__ void compute_chunk(uint32_t As, uint32_t Bs,
                                              int wm, int wn, int lane,
                                              float acc[4][4][4]) {
    constexpr int STRH = TC<KC>::STRH;
    int arow = lane & 15, akoff = (lane >> 4) * 8;
    int brow = (lane & 7) + (lane >> 4) * 8, bkoff = ((lane >> 3) & 1) * 8;
    #pragma unroll
    for (int ks = 0; ks < KC/16; ++ks) {
        int k0 = ks*16;
        uint32_t a[4][4];
        #pragma unroll
        for (int mi = 0; mi < 4; ++mi)
            ldsm_x4(a[mi][0], a[mi][1], a[mi][2], a[mi][3],
                    As + (((wm + mi*16 + arow)*STRH) + k0 + akoff)*2);
        uint32_t bf[4][2];
        #pragma unroll
        for (int njp = 0; njp < 2; ++njp)
            ldsm_x4(bf[njp*2][0], bf[njp*2][1], bf[njp*2+1][0], bf[njp*2+1][1],
                    Bs + (((wn + njp*16 + brow)*STRH) + k0 + bkoff)*2);
        #pragma unroll
        for (int mi = 0; mi < 4; ++mi)
            #pragma unroll
            for (int nj = 0; nj < 4; ++nj)
                mma_f16(acc[mi][nj], a[mi], bf[nj]);
    }
}

// ================= pre-passes =================
__global__ void prep_weights(const float* __restrict__ dw,
                             const float* __restrict__ qw,
                             const float* __restrict__ pw) {
    int i = blockIdx.x * blockDim.x + threadIdx.x;
    if (i < 9*CC*CC) {
        int c = i & 255, o = (i >> 8) & 255, k = i >> 16;
        g_wconv[i] = __float2half(dw[(o*CC + c)*9 + k]);
    }
    if (i < O3*CC) g_wqc[i] = __float2half(qw[i]);
    if (i < CC*CC) g_wpc[i] = __float2half(pw[i]);
}

__global__ __launch_bounds__(256) void pad_transpose(const float* __restrict__ x) {
    __shared__ float Xs[64][65];
    int d = blockIdx.x, b = blockIdx.y, t = threadIdx.x;
    __half* outb = g_xp + ((size_t)(b*DD + d)) * 100 * CC;
    for (int cc = 0; cc < 4; ++cc) {
        int c_base = cc * 64;
        __syncthreads();
        for (int v = t; v < 4096; v += 256) {
            int c = v >> 6, n = v & 63;
            Xs[c][n] = x[((size_t)(b*CC + c_base + c)*DD + d)*64 + n];
        }
        __syncthreads();
        for (int v = t; v < 6400; v += 256) {
            int p = v >> 6, c = v & 63;
            int h = p/10 - 1, w = p%10 - 1;
            float val = 0.f;
            if ((unsigned)h < 8u && (unsigned)w < 8u) val = Xs[c][h*8 + w];
            outb[p*CC + c_base + c] = __float2half(val);
        }
    }
}

// ================= conv v3: resident slab + TRIPLE-buffered W, 1 sync per shift =========
#define CV_STRH 72
#define CV_SLABB 28800
#define CV_WB    18432
#define CV_SMEM3 (CV_SLABB + 3*CV_WB)    // 84096

__global__ __launch_bounds__(256) void conv_mma3(const float* __restrict__ bconv) {
    extern __shared__ __half smemh[];
    uint32_t sb = smem_u32(smemh);
    const uint32_t SLAB = sb;
    uint32_t wbuf[3] = { sb + CV_SLABB, sb + CV_SLABB + CV_WB, sb + CV_SLABB + 2*CV_WB };
    int tid = threadIdx.x, lane = tid & 31, wid = tid >> 5;
    int wm = (wid & 1) * 64, wn = (wid >> 1) * 32;
    int o_base = blockIdx.x * 128;
    int d0 = blockIdx.y * 2;
    int b = blockIdx.z;

    const __half* xpb = g_xp + ((size_t)(b*DD + d0)) * 25600;

    int arowl = lane & 15, akoff = (lane >> 4) * 8;
    uint32_t abase[4];
    #pragma unroll
    for (int mi = 0; mi < 4; ++mi) {
        int m = wm + mi*16 + arowl;
        int slabrow = (m >> 6)*100 + ((m & 63) >> 3)*10 + (m & 7);
        abase[mi] = SLAB + (slabrow*CV_STRH + akoff)*2;
    }
    int brow = (lane & 7) + (lane >> 4) * 8, bkoff = ((lane >> 3) & 1) * 8;

    float acc[4][4][4];
    #pragma unroll
    for (int mi = 0; mi < 4; ++mi)
        #pragma unroll
        for (int nj = 0; nj < 4; ++nj)
            #pragma unroll
            for (int q = 0; q < 4; ++q) acc[mi][nj][q] = 0.f;

    for (int cc = 0; cc < 4; ++cc) {
        int c0 = cc * 64;
        __syncthreads();
        #pragma unroll
        for (int t = 0; t < 7; ++t) {
            int s = tid + t*256;
            if (s < 1600) {
                int row = s >> 3, j = s & 7;
                cpasync16(SLAB + row*144 + j*16,
                          xpb + (size_t)(row/100)*25600 + (row%100)*256 + c0 + j*8);
            }
        }
        cp_commit();
        auto stageW = [&](int k, uint32_t wb) {
            const __half* wkb = g_wconv + k*65536 + (size_t)o_base*256 + c0;
            #pragma unroll
            for (int t = 0; t < 4; ++t) {
                int s = tid + t*256; int row = s >> 3, j = s & 7;
                cpasync16(wb + row*144 + j*16, wkb + row*256 + j*8);
            }
            cp_commit();
        };
        stageW(0, wbuf[0]);
        stageW(1, wbuf[1]);
        for (int k = 0; k < 9; ++k) {
            if (k < 8) cp_wait1(); else cp_wait0();
            __syncthreads();
            if (k + 2 < 9) stageW(k + 2, wbuf[(k + 2) % 3]);
            uint32_t wb = wbuf[k % 3];
            uint32_t shoff = (uint32_t)((k/3)*10 + (k%3)) * 144;
            #pragma unroll
            for (int ks = 0; ks < 4; ++ks) {
                int k0 = ks*16;
                uint32_t a[4][4];
                #pragma unroll
                for (int mi = 0; mi < 4; ++mi)
                    ldsm_x4(a[mi][0], a[mi][1], a[mi][2], a[mi][3],
                            abase[mi] + shoff + k0*2);
                uint32_t bf[4][2];
                #pragma unroll
                for (int njp = 0; njp < 2; ++njp)
                    ldsm_x4(bf[njp*2][0], bf[njp*2][1], bf[njp*2+1][0], bf[njp*2+1][1],
                            wb + (((wn + njp*16 + brow)*CV_STRH) + k0 + bkoff)*2);
                #pragma unroll
                for (int mi = 0; mi < 4; ++mi)
                    #pragma unroll
                    for (int nj = 0; nj < 4; ++nj)
                        mma_f16(acc[mi][nj], a[mi], bf[nj]);
            }
        }
    }

    int lr = lane >> 2, lc = lane & 3;
    #pragma unroll
    for (int mi = 0; mi < 4; ++mi) {
        int m = wm + mi*16 + lr;
        int ng0 = (d0 + (m >> 6))*64 + (m & 63);
        int ng1 = (d0 + ((m+8) >> 6))*64 + ((m+8) & 63);
        __half* r0 = g_xlt + ((size_t)(b*NTOT + ng0))*CC + o_base;
        __half* r1 = g_xlt + ((size_t)(b*NTOT + ng1))*CC + o_base;
        #pragma unroll
        for (int nj = 0; nj < 4; ++nj) {
            int o = wn + nj*8 + lc*2;
            float bv0 = bconv[o_base + o], bv1 = bconv[o_base + o + 1];
            *(__half2*)(r0 + o) = __floats2half2_rn(acc[mi][nj][0] + bv0, acc[mi][nj][1] + bv1);
            *(__half2*)(r1 + o) = __floats2half2_rn(acc[mi][nj][2] + bv0, acc[mi][nj][3] + bv1);
        }
    }
}

// ================= projection GEMM v3: 3-stage multistage, 1 sync per chunk =============
// WHICH==0: A=g_wqc, B=g_xlt, Y=g_qkv(half).  WHICH==1: A=g_wpc, B=g_xat, Y=Yext(float).
#define G3_STRH 72
#define G3_TFH  (128*G3_STRH)
#define G3_STAGEB (2*G3_TFH*2)           // A+B per stage = 36864
#define G3_SMEM (3*G3_STAGEB)            // 110592

template<int OC, int WHICH>
__global__ __launch_bounds__(256) void gemm_mma3(const float* __restrict__ bias,
                                                 float* __restrict__ Yext) {
    extern __shared__ __half smemh[];
    uint32_t sb = smem_u32(smemh);
    int tid = threadIdx.x, lane = tid & 31, wid = tid >> 5;
    int wm = (wid & 1) * 64, wn = (wid >> 1) * 32;
    int o_base = blockIdx.x * 128;
    int n_base = blockIdx.y * 128;
    int b = blockIdx.z;

    const __half* Ap = ((WHICH == 0) ? g_wqc : g_wpc) + (size_t)o_base*256;
    const __half* Bp = ((WHICH == 0) ? g_xlt : g_xat) + ((size_t)b*NTOT + n_base)*256;

    float acc[4][4][4];
    #pragma unroll
    for (int mi = 0; mi < 4; ++mi)
        #pragma unroll
        for (int nj = 0; nj < 4; ++nj)
            #pragma unroll
            for (int q = 0; q < 4; ++q) acc[mi][nj][q] = 0.f;

    auto stage = [&](int chunk, int s) {
        int c0 = chunk * 64;
        uint32_t ab = sb + (uint32_t)s * G3_STAGEB;
        uint32_t bbuf = ab + G3_TFH*2;
        #pragma unroll
        for (int t = 0; t < 4; ++t) {
            int g = tid + t*256; int row = g >> 3, j = g & 7;
            cpasync16(ab + row*144 + j*16, Ap + (size_t)row*256 + c0 + j*8);
            cpasync16(bbuf + row*144 + j*16, Bp + (size_t)row*256 + c0 + j*8);
        }
        cp_commit();
    };

    stage(0, 0);
    stage(1, 1);
    #pragma unroll
    for (int i = 0; i < 4; ++i) {
        if (i < 3) cp_wait1(); else cp_wait0();
        __syncthreads();                       // buf (i+2)%3 fully consumed (iter i-1)
        if (i + 2 < 4) stage(i + 2, (i + 2) % 3);
        uint32_t ab = sb + (uint32_t)(i % 3) * G3_STAGEB;
        compute_chunk<64>(ab, ab + G3_TFH*2, wm, wn, lane, acc);
    }

    int lr = lane >> 2, lc = lane & 3;
    #pragma unroll
    for (int mi = 0; mi < 4; ++mi) {
        int o0 = o_base + wm + mi*16 + lr;
        float bv0 = bias[o0], bv1 = bias[o0 + 8];
        #pragma unroll
        for (int nj = 0; nj < 4; ++nj) {
            int col = wn + nj*8 + lc*2;
            if (WHICH == 0) {
                __half* y0 = g_qkv + ((size_t)b*OC + o0)*NTOT + n_base;
                __half* y1 = g_qkv + ((size_t)b*OC + o0 + 8)*NTOT + n_base;
                *(__half2*)(y0 + col) = __floats2half2_rn(acc[mi][nj][0] + bv0, acc[mi][nj][1] + bv0);
                *(__half2*)(y1 + col) = __floats2half2_rn(acc[mi][nj][2] + bv1, acc[mi][nj][3] + bv1);
            } else {
                float* y0 = Yext + ((size_t)b*OC + o0)*NTOT + n_base;
                float* y1 = Yext + ((size_t)b*OC + o0 + 8)*NTOT + n_base;
                float2 v0 = { acc[mi][nj][0] + bv0, acc[mi][nj][1] + bv0 };
                float2 v1 = { acc[mi][nj][2] + bv1, acc[mi][nj][3] + bv1 };
                *(float2*)(y0 + col) = v0;
                *(float2*)(y1 + col) = v1;
            }
        }
    }
}

// ================= KC=32 2-stage fallbacks (40KB smem, no opt-in) =================
template<int KC>
__global__ __launch_bounds__(256) void conv_mma(const float* __restrict__ bconv) {
    constexpr int TFH  = TC<KC>::TFH;
    constexpr int ROWB = TC<KC>::STRH * 2;
    extern __shared__ __half smemh[];
    uint32_t sb = smem_u32(smemh);
    int tid = threadIdx.x, lane = tid & 31, wid = tid >> 5;
    int wm = (wid & 1) * 64, wn = (wid >> 1) * 32;
    int o_base = blockIdx.x * 128;
    int d0 = blockIdx.y * 2;
    int b = blockIdx.z;

    const __half* xpb = g_xp + ((size_t)(b*DD + d0)) * 25600;

    float acc[4][4][4];
    #pragma unroll
    for (int mi = 0; mi < 4; ++mi)
        #pragma unroll
        for (int nj = 0; nj < 4; ++nj)
            #pragma unroll
            for (int q = 0; q < 4; ++q) acc[mi][nj][q] = 0.f;

    constexpr int CPK = 256/KC;
    auto stage = [&](int chunk, int buf) {
        int k = chunk / CPK, c0 = (chunk % CPK) * KC;
        int kh = k / 3, kw = k % 3;
        uint32_t ab = sb + (uint32_t)buf * (2*TFH*2);
        uint32_t bbuf = ab + TFH*2;
        const __half* wkb = g_wconv + k*65536 + (size_t)o_base*256 + c0;
        #pragma unroll
        for (int t = 0; t < KC/16; ++t) {
            int g = tid + t*256; int row = g / (KC/8), j = g % (KC/8);
            int dl = row >> 6, n = row & 63, h = n >> 3, w = n & 7;
            int p = (h + kh)*10 + (w + kw);
            cpasync16(ab + row*ROWB + j*16, xpb + (size_t)dl*25600 + p*256 + c0 + j*8);
            cpasync16(bbuf + row*ROWB + j*16, wkb + row*256 + j*8);
        }
        cp_commit();
    };

    constexpr int NCH = 9 * CPK;
    stage(0, 0);
    for (int i = 0; i < NCH; ++i) {
        int buf = i & 1;
        if (i < NCH-1) stage(i + 1, buf ^ 1);
        if (i < NCH-1) cp_wait1(); else cp_wait0();
        __syncthreads();
        uint32_t ab = sb + (uint32_t)buf * (2*TFH*2);
        compute_chunk<KC>(ab, ab + TFH*2, wm, wn, lane, acc);
        __syncthreads();
    }

    int lr = lane >> 2, lc = lane & 3;
    #pragma unroll
    for (int mi = 0; mi < 4; ++mi) {
        int m = wm + mi*16 + lr;
        int ng0 = (d0 + (m >> 6))*64 + (m & 63);
        int ng1 = (d0 + ((m+8) >> 6))*64 + ((m+8) & 63);
        __half* r0 = g_xlt + ((size_t)(b*NTOT + ng0))*CC + o_base;
        __half* r1 = g_xlt + ((size_t)(b*NTOT + ng1))*CC + o_base;
        #pragma unroll
        for (int nj = 0; nj < 4; ++nj) {
            int o = wn + nj*8 + lc*2;
            float bv0 = bconv[o_base + o], bv1 = bconv[o_base + o + 1];
            *(__half2*)(r0 + o) = __floats2half2_rn(acc[mi][nj][0] + bv0, acc[mi][nj][1] + bv1);
            *(__half2*)(r1 + o) = __floats2half2_rn(acc[mi][nj][2] + bv0, acc[mi][nj][3] + bv1);
        }
    }
}

template<int OC, int WHICH, int KC>
__global__ __launch_bounds__(256) void gemm_mma(const float* __restrict__ bias,
                                                float* __restrict__ Yext) {
    constexpr int TFH  = TC<KC>::TFH;
    constexpr int ROWB = TC<KC>::STRH * 2;
    extern __shared__ __half smemh[];
    uint32_t sb = smem_u32(smemh);
    int tid = threadIdx.x, lane = tid & 31, wid = tid >> 5;
    int wm = (wid & 1) * 64, wn = (wid >> 1) * 32;
    int o_base = blockIdx.x * 128;
    int n_base = blockIdx.y * 128;
    int b = blockIdx.z;

    const __half* Ap = ((WHICH == 0) ? g_wqc : g_wpc) + (size_t)o_base*256;
    const __half* Bp = ((WHICH == 0) ? g_xlt : g_xat) + ((size_t)b*NTOT + n_base)*256;

    float acc[4][4][4];
    #pragma unroll
    for (int mi = 0; mi < 4; ++mi)
        #pragma unroll
        for (int nj = 0; nj < 4; ++nj)
            #pragma unroll
            for (int q = 0; q < 4; ++q) acc[mi][nj][q] = 0.f;

    auto stage = [&](int chunk, int buf) {
        int c0 = chunk * KC;
        uint32_t ab = sb + (uint32_t)buf * (2*TFH*2);
        uint32_t bbuf = ab + TFH*2;
        #pragma unroll
        for (int t = 0; t < KC/16; ++t) {
            int g = tid + t*256; int row = g / (KC/8), j = g % (KC/8);
            cpasync16(ab + row*ROWB + j*16, Ap + (size_t)row*256 + c0 + j*8);
            cpasync16(bbuf + row*ROWB + j*16, Bp + (size_t)row*256 + c0 + j*8);
        }
        cp_commit();
    };

    constexpr int NCH = 256/KC;
    stage(0, 0);
    for (int i = 0; i < NCH; ++i) {
        int buf = i & 1;
        if (i < NCH-1) stage(i + 1, buf ^ 1);
        if (i < NCH-1) cp_wait1(); else cp_wait0();
        __syncthreads();
        uint32_t ab = sb + (uint32_t)buf * (2*TFH*2);
        compute_chunk<KC>(ab, ab + TFH*2, wm, wn, lane, acc);
        __syncthreads();
    }

    int lr = lane >> 2, lc = lane & 3;
    #pragma unroll
    for (int mi = 0; mi < 4; ++mi) {
        int o0 = o_base + wm + mi*16 + lr;
        float bv0 = bias[o0], bv1 = bias[o0 + 8];
        #pragma unroll
        for (int nj = 0; nj < 4; ++nj) {
            int col = wn + nj*8 + lc*2;
            if (WHICH == 0) {
                __half* y0 = g_qkv + ((size_t)b*OC + o0)*NTOT + n_base;
                __half* y1 = g_qkv + ((size_t)b*OC + o0 + 8)*NTOT + n_base;
                *(__half2*)(y0 + col) = __floats2half2_rn(acc[mi][nj][0] + bv0, acc[mi][nj][1] + bv0);
                *(__half2*)(y1 + col) = __floats2half2_rn(acc[mi][nj][2] + bv1, acc[mi][nj][3] + bv1);
            } else {
                float* y0 = Yext + ((size_t)b*OC + o0)*NTOT + n_base;
                float* y1 = Yext + ((size_t)b*OC + o0 + 8)*NTOT + n_base;
                float2 v0 = { acc[mi][nj][0] + bv0, acc[mi][nj][1] + bv0 };
                float2 v1 = { acc[mi][nj][2] + bv1, acc[mi][nj][3] + bv1 };
                *(float2*)(y0 + col) = v0;
                *(float2*)(y1 + col) = v1;
            }
        }
    }
}

// ================= attention (fp32 f32x2 math; q direct from gmem; k/v fp32 smem) =======
__global__ __launch_bounds__(64) void attn_kernel(const float* __restrict__ rpb) {
    __shared__ float ks[2048];
    __shared__ float vs[2048];
    __shared__ float rpb_s[225];

    int head = blockIdx.x, d = blockIdx.y, b = blockIdx.z;
    int t = threadIdx.x;

    const __half* base = g_qkv + ((size_t)(b*O3 + head*HDIM))*NTOT + d*64;
    for (int i = t; i < 2048; i += 64) {
        int hd = i >> 6, n = i & 63;
        ks[i] = __half2float(base[(size_t)(256 + hd)*NTOT + n]);
        vs[i] = __half2float(base[(size_t)(512 + hd)*NTOT + n]);
    }
    for (int i = t; i < 225; i += 64) rpb_s[i] = rpb[i*HEADS + head];

    const int n = t, hn = n >> 3, wn = n & 7;
    const float scale = 0.17677669529663687f;

    // q: coalesced direct gmem loads (thread n reads its own column)
    float qr[32];
    #pragma unroll
    for (int hd = 0; hd < 32; ++hd) qr[hd] = __half2float(base[(size_t)hd*NTOT + n]);
    __syncthreads();

    u64t acc2[32];
    #pragma unroll
    for (int j = 0; j < 32; ++j) acc2[j] = 0ull;
    #pragma unroll
    for (int hd = 0; hd < 32; ++hd) {
        u64t qd = pk2(qr[hd], qr[hd]);
        const ulonglong2* kp = (const ulonglong2*)&ks[hd*64];
        #pragma unroll
        for (int m4 = 0; m4 < 16; ++m4) {
            ulonglong2 kk = kp[m4];
            fma2(acc2[m4*2],     qd, kk.x);
            fma2(acc2[m4*2 + 1], qd, kk.y);
        }
    }

    float sc[64];
    #pragma unroll
    for (int j = 0; j < 32; ++j) upk2(acc2[j], sc[2*j], sc[2*j + 1]);
    #pragma unroll
    for (int m = 0; m < 64; ++m) {
        int di = hn - (m >> 3) + 7;
        int dj = wn - (m & 7) + 7;
        sc[m] = sc[m]*scale + rpb_s[di*15 + dj];
    }

    float mx = -1e30f;
    #pragma unroll
    for (int m = 0; m < 64; ++m) mx = fmaxf(mx, sc[m]);
    float sum = 0.f;
    #pragma unroll
    for (int m = 0; m < 64; ++m) { sc[m] = __expf(sc[m] - mx); sum += sc[m]; }
    float inv = 1.f / sum;

    #pragma unroll
    for (int j = 0; j < 32; ++j) acc2[j] = pk2(sc[2*j]*inv, sc[2*j + 1]*inv);

    __half* ysl = g_xat + ((size_t)(b*NTOT + d*64 + n))*CC + head*HDIM;
    #pragma unroll
    for (int hd4 = 0; hd4 < 8; ++hd4) {
        float op[4];
        #pragma unroll
        for (int q = 0; q < 4; ++q) {
            int hd = hd4*4 + q;
            u64t o2 = 0ull;
            const ulonglong2* vp = (const ulonglong2*)&vs[hd*64];
            #pragma unroll
            for (int m4 = 0; m4 < 16; ++m4) {
                ulonglong2 vv = vp[m4];
                fma2(o2, acc2[m4*2],     vv.x);
                fma2(o2, acc2[m4*2 + 1], vv.y);
            }
            float lo, hi; upk2(o2, lo, hi);
            op[q] = lo + hi;
        }
        *(__half2*)(ysl + hd4*4)     = __floats2half2_rn(op[0], op[1]);
        *(__half2*)(ysl + hd4*4 + 2) = __floats2half2_rn(op[2], op[3]);
    }
}

// ================= launch =================
extern "C" void kernel_launch(void* const* d_in, const int* in_sizes, int n_in,
                              void* d_out, int out_size) {
    const float* x   = (const float*)d_in[0];
    const float* dw  = (const float*)d_in[1];
    const float* dwb = (const float*)d_in[2];
    const float* qw  = (const float*)d_in[3];
    const float* qb  = (const float*)d_in[4];
    const float* pw  = (const float*)d_in[5];
    const float* pb  = (const float*)d_in[6];
    const float* rpb = (const float*)d_in[7];
    float* out = (float*)d_out;

    bool big = true;
    big &= cudaFuncSetAttribute(conv_mma3, cudaFuncAttributeMaxDynamicSharedMemorySize, CV_SMEM3) == cudaSuccess;
    big &= cudaFuncSetAttribute(gemm_mma3<O3,0>, cudaFuncAttributeMaxDynamicSharedMemorySize, G3_SMEM) == cudaSuccess;
    big &= cudaFuncSetAttribute(gemm_mma3<CC,1>, cudaFuncAttributeMaxDynamicSharedMemorySize, G3_SMEM) == cudaSuccess;

    prep_weights<<<(9*CC*CC + 255)/256, 256>>>(dw, qw, pw);
    pad_transpose<<<dim3(DD, BB), 256>>>(x);
    if (big) {
        conv_mma3<<<dim3(2, 50, BB), 256, CV_SMEM3>>>(dwb);
        gemm_mma3<O3,0><<<dim3(6, 50, BB), 256, G3_SMEM>>>(qb, nullptr);
    } else {
        conv_mma<32><<<dim3(2, 50, BB), 256, TC<32>::SMEMB>>>(dwb);
        gemm_mma<O3,0,32><<<dim3(6, 50, BB), 256, TC<32>::SMEMB>>>(qb, nullptr);
    }
    attn_kernel<<<dim3(HEADS, DD, BB), 64>>>(rpb);
    if (big) {
        gemm_mma3<CC,1><<<dim3(2, 50, BB), 256, G3_SMEM>>>(pb, out);
    } else {
        gemm_mma<CC,1,32><<<dim3(2, 50, BB), 256, TC<32>::SMEMB>>>(pb, out);
    }
}

// round 16
// speedup vs baseline: 1.5440x; 1.5440x over previous
#include <cuda_runtime.h>
#include <cuda_fp16.h>
#include <cstdint>

// ---------------- problem constants ----------------
#define BB 8
#define CC 256
#define DD 100
#define NN 64
#define HEADS 8
#define HDIM 32
#define O3 768
#define NTOT 6400      // D*N per batch

// ---------------- device scratch (referenced ONLY from device code) ----------------
__device__ __half g_xp  [BB*DD*100*CC];  // padded transposed input [b][d][p100][c]
__device__ __half g_xlt [BB*NTOT*CC];    // conv out transposed [b][n][c]
__device__ __half g_qkv [BB*O3*NTOT];    // qkv [b][o][ntot]
__device__ __half g_xat [BB*NTOT*CC];    // attn out transposed [b][n][c]
__device__ __half g_wconv[9*CC*CC];      // [k][o][c]
__device__ __half g_wqc [O3*CC];         // qkv_w
__device__ __half g_wpc [CC*CC];         // proj_w

// ---------------- helpers ----------------
typedef unsigned long long u64t;

__device__ __forceinline__ uint32_t smem_u32(const void* p) {
    uint32_t a;
    asm("{ .reg .u64 t; cvta.to.shared.u64 t, %1; cvt.u32.u64 %0, t; }" : "=r"(a) : "l"(p));
    return a;
}
__device__ __forceinline__ void cpasync16(uint32_t dst, const void* src) {
    asm volatile("cp.async.cg.shared.global [%0], [%1], 16;" :: "r"(dst), "l"(src) : "memory");
}
__device__ __forceinline__ void cp_commit() { asm volatile("cp.async.commit_group;" ::: "memory"); }
__device__ __forceinline__ void cp_wait1()  { asm volatile("cp.async.wait_group 1;" ::: "memory"); }
__device__ __forceinline__ void cp_wait0()  { asm volatile("cp.async.wait_group 0;" ::: "memory"); }

__device__ __forceinline__ u64t pk2(float lo, float hi) {
    u64t r; asm("mov.b64 %0,{%1,%2};" : "=l"(r) : "f"(lo), "f"(hi)); return r;
}
__device__ __forceinline__ void fma2(u64t& d, u64t a, u64t b) {
    asm("fma.rn.f32x2 %0,%1,%2,%0;" : "+l"(d) : "l"(a), "l"(b));
}
__device__ __forceinline__ void upk2(u64t v, float& lo, float& hi) {
    asm("mov.b64 {%0,%1},%2;" : "=f"(lo), "=f"(hi) : "l"(v));
}

__device__ __forceinline__ void mma_f16(float c[4], const uint32_t a[4], const uint32_t b[2]) {
    asm volatile(
        "mma.sync.aligned.m16n8k16.row.col.f32.f16.f16.f32 "
        "{%0,%1,%2,%3}, {%4,%5,%6,%7}, {%8,%9}, {%0,%1,%2,%3};"
        : "+f"(c[0]), "+f"(c[1]), "+f"(c[2]), "+f"(c[3])
        : "r"(a[0]), "r"(a[1]), "r"(a[2]), "r"(a[3]), "r"(b[0]), "r"(b[1]));
}
__device__ __forceinline__ void ldsm_x4(uint32_t& r0, uint32_t& r1, uint32_t& r2, uint32_t& r3,
                                        uint32_t addr) {
    asm volatile("ldmatrix.sync.aligned.m8n8.x4.shared.b16 {%0,%1,%2,%3}, [%4];"
                 : "=r"(r0), "=r"(r1), "=r"(r2), "=r"(r3) : "r"(addr));
}

// generic GEMM tiles: 128 rows x KC halves; row stride KC+8 halves
template<int KC> struct TC {
    static constexpr int STRH  = KC + 8;
    static constexpr int TFH   = 128 * STRH;
    static constexpr int SMEMB = 4 * TFH * 2;
};

// warp-tile MMA over one staged 128xKC half chunk pair; ldmatrix fragment loads
template<int KC>
__device__ __forceinline__ void compute_chunk(uint32_t As, uint32_t Bs,
                                              int wm, int wn, int lane,
                                              float acc[4][4][4]) {
    constexpr int STRH = TC<KC>::STRH;
    int arow = lane & 15, akoff = (lane >> 4) * 8;
    int brow = (lane & 7) + (lane >> 4) * 8, bkoff = ((lane >> 3) & 1) * 8;
    #pragma unroll
    for (int ks = 0; ks < KC/16; ++ks) {
        int k0 = ks*16;
        uint32_t a[4][4];
        #pragma unroll
        for (int mi = 0; mi < 4; ++mi)
            ldsm_x4(a[mi][0], a[mi][1], a[mi][2], a[mi][3],
                    As + (((wm + mi*16 + arow)*STRH) + k0 + akoff)*2);
        uint32_t bf[4][2];
        #pragma unroll
        for (int njp = 0; njp < 2; ++njp)
            ldsm_x4(bf[njp*2][0], bf[njp*2][1], bf[njp*2+1][0], bf[njp*2+1][1],
                    Bs + (((wn + njp*16 + brow)*STRH) + k0 + bkoff)*2);
        #pragma unroll
        for (int mi = 0; mi < 4; ++mi)
            #pragma unroll
            for (int nj = 0; nj < 4; ++nj)
                mma_f16(acc[mi][nj], a[mi], bf[nj]);
    }
}

// ================= pre-passes =================
__global__ void prep_weights(const float* __restrict__ dw,
                             const float* __restrict__ qw,
                             const float* __restrict__ pw) {
    int i = blockIdx.x * blockDim.x + threadIdx.x;
    if (i < 9*CC*CC) {
        int c = i & 255, o = (i >> 8) & 255, k = i >> 16;
        g_wconv[i] = __float2half(dw[(o*CC + c)*9 + k]);
    }
    if (i < O3*CC) g_wqc[i] = __float2half(qw[i]);
    if (i < CC*CC) g_wpc[i] = __float2half(pw[i]);
}

__global__ __launch_bounds__(256) void pad_transpose(const float* __restrict__ x) {
    __shared__ float Xs[64][65];
    int d = blockIdx.x, b = blockIdx.y, t = threadIdx.x;
    __half* outb = g_xp + ((size_t)(b*DD + d)) * 100 * CC;
    for (int cc = 0; cc < 4; ++cc) {
        int c_base = cc * 64;
        __syncthreads();
        for (int v = t; v < 4096; v += 256) {
            int c = v >> 6, n = v & 63;
            Xs[c][n] = x[((size_t)(b*CC + c_base + c)*DD + d)*64 + n];
        }
        __syncthreads();
        for (int v = t; v < 6400; v += 256) {
            int p = v >> 6, c = v & 63;
            int h = p/10 - 1, w = p%10 - 1;
            float val = 0.f;
            if ((unsigned)h < 8u && (unsigned)w < 8u) val = Xs[c][h*8 + w];
            outb[p*CC + c_base + c] = __float2half(val);
        }
    }
}

// ================= conv v3: resident slab + TRIPLE-buffered W, 1 sync per shift =========
#define CV_STRH 72
#define CV_SLABB 28800
#define CV_WB    18432
#define CV_SMEM3 (CV_SLABB + 3*CV_WB)    // 84096

__global__ __launch_bounds__(256) void conv_mma3(const float* __restrict__ bconv) {
    extern __shared__ __half smemh[];
    uint32_t sb = smem_u32(smemh);
    const uint32_t SLAB = sb;
    uint32_t wbuf[3] = { sb + CV_SLABB, sb + CV_SLABB + CV_WB, sb + CV_SLABB + 2*CV_WB };
    int tid = threadIdx.x, lane = tid & 31, wid = tid >> 5;
    int wm = (wid & 1) * 64, wn = (wid >> 1) * 32;
    int o_base = blockIdx.x * 128;
    int d0 = blockIdx.y * 2;
    int b = blockIdx.z;

    const __half* xpb = g_xp + ((size_t)(b*DD + d0)) * 25600;

    int arowl = lane & 15, akoff = (lane >> 4) * 8;
    uint32_t abase[4];
    #pragma unroll
    for (int mi = 0; mi < 4; ++mi) {
        int m = wm + mi*16 + arowl;
        int slabrow = (m >> 6)*100 + ((m & 63) >> 3)*10 + (m & 7);
        abase[mi] = SLAB + (slabrow*CV_STRH + akoff)*2;
    }
    int brow = (lane & 7) + (lane >> 4) * 8, bkoff = ((lane >> 3) & 1) * 8;

    float acc[4][4][4];
    #pragma unroll
    for (int mi = 0; mi < 4; ++mi)
        #pragma unroll
        for (int nj = 0; nj < 4; ++nj)
            #pragma unroll
            for (int q = 0; q < 4; ++q) acc[mi][nj][q] = 0.f;

    for (int cc = 0; cc < 4; ++cc) {
        int c0 = cc * 64;
        __syncthreads();
        #pragma unroll
        for (int t = 0; t < 7; ++t) {
            int s = tid + t*256;
            if (s < 1600) {
                int row = s >> 3, j = s & 7;
                cpasync16(SLAB + row*144 + j*16,
                          xpb + (size_t)(row/100)*25600 + (row%100)*256 + c0 + j*8);
            }
        }
        cp_commit();
        auto stageW = [&](int k, uint32_t wb) {
            const __half* wkb = g_wconv + k*65536 + (size_t)o_base*256 + c0;
            #pragma unroll
            for (int t = 0; t < 4; ++t) {
                int s = tid + t*256; int row = s >> 3, j = s & 7;
                cpasync16(wb + row*144 + j*16, wkb + row*256 + j*8);
            }
            cp_commit();
        };
        stageW(0, wbuf[0]);
        stageW(1, wbuf[1]);
        for (int k = 0; k < 9; ++k) {
            if (k < 8) cp_wait1(); else cp_wait0();
            __syncthreads();
            if (k + 2 < 9) stageW(k + 2, wbuf[(k + 2) % 3]);
            uint32_t wb = wbuf[k % 3];
            uint32_t shoff = (uint32_t)((k/3)*10 + (k%3)) * 144;
            #pragma unroll
            for (int ks = 0; ks < 4; ++ks) {
                int k0 = ks*16;
                uint32_t a[4][4];
                #pragma unroll
                for (int mi = 0; mi < 4; ++mi)
                    ldsm_x4(a[mi][0], a[mi][1], a[mi][2], a[mi][3],
                            abase[mi] + shoff + k0*2);
                uint32_t bf[4][2];
                #pragma unroll
                for (int njp = 0; njp < 2; ++njp)
                    ldsm_x4(bf[njp*2][0], bf[njp*2][1], bf[njp*2+1][0], bf[njp*2+1][1],
                            wb + (((wn + njp*16 + brow)*CV_STRH) + k0 + bkoff)*2);
                #pragma unroll
                for (int mi = 0; mi < 4; ++mi)
                    #pragma unroll
                    for (int nj = 0; nj < 4; ++nj)
                        mma_f16(acc[mi][nj], a[mi], bf[nj]);
            }
        }
    }

    int lr = lane >> 2, lc = lane & 3;
    #pragma unroll
    for (int mi = 0; mi < 4; ++mi) {
        int m = wm + mi*16 + lr;
        int ng0 = (d0 + (m >> 6))*64 + (m & 63);
        int ng1 = (d0 + ((m+8) >> 6))*64 + ((m+8) & 63);
        __half* r0 = g_xlt + ((size_t)(b*NTOT + ng0))*CC + o_base;
        __half* r1 = g_xlt + ((size_t)(b*NTOT + ng1))*CC + o_base;
        #pragma unroll
        for (int nj = 0; nj < 4; ++nj) {
            int o = wn + nj*8 + lc*2;
            float bv0 = bconv[o_base + o], bv1 = bconv[o_base + o + 1];
            *(__half2*)(r0 + o) = __floats2half2_rn(acc[mi][nj][0] + bv0, acc[mi][nj][1] + bv1);
            *(__half2*)(r1 + o) = __floats2half2_rn(acc[mi][nj][2] + bv0, acc[mi][nj][3] + bv1);
        }
    }
}

// ================= projection GEMM v3: 3-stage multistage, 1 sync per chunk =============
// WHICH==0: A=g_wqc, B=g_xlt, Y=g_qkv(half).  WHICH==1: A=g_wpc, B=g_xat, Y=Yext(float).
#define G3_STRH 72
#define G3_TFH  (128*G3_STRH)
#define G3_STAGEB (2*G3_TFH*2)           // A+B per stage = 36864
#define G3_SMEM (3*G3_STAGEB)            // 110592

template<int OC, int WHICH>
__global__ __launch_bounds__(256) void gemm_mma3(const float* __restrict__ bias,
                                                 float* __restrict__ Yext) {
    extern __shared__ __half smemh[];
    uint32_t sb = smem_u32(smemh);
    int tid = threadIdx.x, lane = tid & 31, wid = tid >> 5;
    int wm = (wid & 1) * 64, wn = (wid >> 1) * 32;
    int o_base = blockIdx.x * 128;
    int n_base = blockIdx.y * 128;
    int b = blockIdx.z;

    const __half* Ap = ((WHICH == 0) ? g_wqc : g_wpc) + (size_t)o_base*256;
    const __half* Bp = ((WHICH == 0) ? g_xlt : g_xat) + ((size_t)b*NTOT + n_base)*256;

    float acc[4][4][4];
    #pragma unroll
    for (int mi = 0; mi < 4; ++mi)
        #pragma unroll
        for (int nj = 0; nj < 4; ++nj)
            #pragma unroll
            for (int q = 0; q < 4; ++q) acc[mi][nj][q] = 0.f;

    auto stage = [&](int chunk, int s) {
        int c0 = chunk * 64;
        uint32_t ab = sb + (uint32_t)s * G3_STAGEB;
        uint32_t bbuf = ab + G3_TFH*2;
        #pragma unroll
        for (int t = 0; t < 4; ++t) {
            int g = tid + t*256; int row = g >> 3, j = g & 7;
            cpasync16(ab + row*144 + j*16, Ap + (size_t)row*256 + c0 + j*8);
            cpasync16(bbuf + row*144 + j*16, Bp + (size_t)row*256 + c0 + j*8);
        }
        cp_commit();
    };

    stage(0, 0);
    stage(1, 1);
    #pragma unroll
    for (int i = 0; i < 4; ++i) {
        if (i < 3) cp_wait1(); else cp_wait0();
        __syncthreads();                       // buf (i+2)%3 fully consumed (iter i-1)
        if (i + 2 < 4) stage(i + 2, (i + 2) % 3);
        uint32_t ab = sb + (uint32_t)(i % 3) * G3_STAGEB;
        compute_chunk<64>(ab, ab + G3_TFH*2, wm, wn, lane, acc);
    }

    int lr = lane >> 2, lc = lane & 3;
    #pragma unroll
    for (int mi = 0; mi < 4; ++mi) {
        int o0 = o_base + wm + mi*16 + lr;
        float bv0 = bias[o0], bv1 = bias[o0 + 8];
        #pragma unroll
        for (int nj = 0; nj < 4; ++nj) {
            int col = wn + nj*8 + lc*2;
            if (WHICH == 0) {
                __half* y0 = g_qkv + ((size_t)b*OC + o0)*NTOT + n_base;
                __half* y1 = g_qkv + ((size_t)b*OC + o0 + 8)*NTOT + n_base;
                *(__half2*)(y0 + col) = __floats2half2_rn(acc[mi][nj][0] + bv0, acc[mi][nj][1] + bv0);
                *(__half2*)(y1 + col) = __floats2half2_rn(acc[mi][nj][2] + bv1, acc[mi][nj][3] + bv1);
            } else {
                float* y0 = Yext + ((size_t)b*OC + o0)*NTOT + n_base;
                float* y1 = Yext + ((size_t)b*OC + o0 + 8)*NTOT + n_base;
                float2 v0 = { acc[mi][nj][0] + bv0, acc[mi][nj][1] + bv0 };
                float2 v1 = { acc[mi][nj][2] + bv1, acc[mi][nj][3] + bv1 };
                *(float2*)(y0 + col) = v0;
                *(float2*)(y1 + col) = v1;
            }
        }
    }
}

// ================= KC=32 2-stage fallbacks (40KB smem, no opt-in) =================
template<int KC>
__global__ __launch_bounds__(256) void conv_mma(const float* __restrict__ bconv) {
    constexpr int TFH  = TC<KC>::TFH;
    constexpr int ROWB = TC<KC>::STRH * 2;
    extern __shared__ __half smemh[];
    uint32_t sb = smem_u32(smemh);
    int tid = threadIdx.x, lane = tid & 31, wid = tid >> 5;
    int wm = (wid & 1) * 64, wn = (wid >> 1) * 32;
    int o_base = blockIdx.x * 128;
    int d0 = blockIdx.y * 2;
    int b = blockIdx.z;

    const __half* xpb = g_xp + ((size_t)(b*DD + d0)) * 25600;

    float acc[4][4][4];
    #pragma unroll
    for (int mi = 0; mi < 4; ++mi)
        #pragma unroll
        for (int nj = 0; nj < 4; ++nj)
            #pragma unroll
            for (int q = 0; q < 4; ++q) acc[mi][nj][q] = 0.f;

    constexpr int CPK = 256/KC;
    auto stage = [&](int chunk, int buf) {
        int k = chunk / CPK, c0 = (chunk % CPK) * KC;
        int kh = k / 3, kw = k % 3;
        uint32_t ab = sb + (uint32_t)buf * (2*TFH*2);
        uint32_t bbuf = ab + TFH*2;
        const __half* wkb = g_wconv + k*65536 + (size_t)o_base*256 + c0;
        #pragma unroll
        for (int t = 0; t < KC/16; ++t) {
            int g = tid + t*256; int row = g / (KC/8), j = g % (KC/8);
            int dl = row >> 6, n = row & 63, h = n >> 3, w = n & 7;
            int p = (h + kh)*10 + (w + kw);
            cpasync16(ab + row*ROWB + j*16, xpb + (size_t)dl*25600 + p*256 + c0 + j*8);
            cpasync16(bbuf + row*ROWB + j*16, wkb + row*256 + j*8);
        }
        cp_commit();
    };

    constexpr int NCH = 9 * CPK;
    stage(0, 0);
    for (int i = 0; i < NCH; ++i) {
        int buf = i & 1;
        if (i < NCH-1) stage(i + 1, buf ^ 1);
        if (i < NCH-1) cp_wait1(); else cp_wait0();
        __syncthreads();
        uint32_t ab = sb + (uint32_t)buf * (2*TFH*2);
        compute_chunk<KC>(ab, ab + TFH*2, wm, wn, lane, acc);
        __syncthreads();
    }

    int lr = lane >> 2, lc = lane & 3;
    #pragma unroll
    for (int mi = 0; mi < 4; ++mi) {
        int m = wm + mi*16 + lr;
        int ng0 = (d0 + (m >> 6))*64 + (m & 63);
        int ng1 = (d0 + ((m+8) >> 6))*64 + ((m+8) & 63);
        __half* r0 = g_xlt + ((size_t)(b*NTOT + ng0))*CC + o_base;
        __half* r1 = g_xlt + ((size_t)(b*NTOT + ng1))*CC + o_base;
        #pragma unroll
        for (int nj = 0; nj < 4; ++nj) {
            int o = wn + nj*8 + lc*2;
            float bv0 = bconv[o_base + o], bv1 = bconv[o_base + o + 1];
            *(__half2*)(r0 + o) = __floats2half2_rn(acc[mi][nj][0] + bv0, acc[mi][nj][1] + bv1);
            *(__half2*)(r1 + o) = __floats2half2_rn(acc[mi][nj][2] + bv0, acc[mi][nj][3] + bv1);
        }
    }
}

template<int OC, int WHICH, int KC>
__global__ __launch_bounds__(256) void gemm_mma(const float* __restrict__ bias,
                                                float* __restrict__ Yext) {
    constexpr int TFH  = TC<KC>::TFH;
    constexpr int ROWB = TC<KC>::STRH * 2;
    extern __shared__ __half smemh[];
    uint32_t sb = smem_u32(smemh);
    int tid = threadIdx.x, lane = tid & 31, wid = tid >> 5;
    int wm = (wid & 1) * 64, wn = (wid >> 1) * 32;
    int o_base = blockIdx.x * 128;
    int n_base = blockIdx.y * 128;
    int b = blockIdx.z;

    const __half* Ap = ((WHICH == 0) ? g_wqc : g_wpc) + (size_t)o_base*256;
    const __half* Bp = ((WHICH == 0) ? g_xlt : g_xat) + ((size_t)b*NTOT + n_base)*256;

    float acc[4][4][4];
    #pragma unroll
    for (int mi = 0; mi < 4; ++mi)
        #pragma unroll
        for (int nj = 0; nj < 4; ++nj)
            #pragma unroll
            for (int q = 0; q < 4; ++q) acc[mi][nj][q] = 0.f;

    auto stage = [&](int chunk, int buf) {
        int c0 = chunk * KC;
        uint32_t ab = sb + (uint32_t)buf * (2*TFH*2);
        uint32_t bbuf = ab + TFH*2;
        #pragma unroll
        for (int t = 0; t < KC/16; ++t) {
            int g = tid + t*256; int row = g / (KC/8), j = g % (KC/8);
            cpasync16(ab + row*ROWB + j*16, Ap + (size_t)row*256 + c0 + j*8);
            cpasync16(bbuf + row*ROWB + j*16, Bp + (size_t)row*256 + c0 + j*8);
        }
        cp_commit();
    };

    constexpr int NCH = 256/KC;
    stage(0, 0);
    for (int i = 0; i < NCH; ++i) {
        int buf = i & 1;
        if (i < NCH-1) stage(i + 1, buf ^ 1);
        if (i < NCH-1) cp_wait1(); else cp_wait0();
        __syncthreads();
        uint32_t ab = sb + (uint32_t)buf * (2*TFH*2);
        compute_chunk<KC>(ab, ab + TFH*2, wm, wn, lane, acc);
        __syncthreads();
    }

    int lr = lane >> 2, lc = lane & 3;
    #pragma unroll
    for (int mi = 0; mi < 4; ++mi) {
        int o0 = o_base + wm + mi*16 + lr;
        float bv0 = bias[o0], bv1 = bias[o0 + 8];
        #pragma unroll
        for (int nj = 0; nj < 4; ++nj) {
            int col = wn + nj*8 + lc*2;
            if (WHICH == 0) {
                __half* y0 = g_qkv + ((size_t)b*OC + o0)*NTOT + n_base;
                __half* y1 = g_qkv + ((size_t)b*OC + o0 + 8)*NTOT + n_base;
                *(__half2*)(y0 + col) = __floats2half2_rn(acc[mi][nj][0] + bv0, acc[mi][nj][1] + bv0);
                *(__half2*)(y1 + col) = __floats2half2_rn(acc[mi][nj][2] + bv1, acc[mi][nj][3] + bv1);
            } else {
                float* y0 = Yext + ((size_t)b*OC + o0)*NTOT + n_base;
                float* y1 = Yext + ((size_t)b*OC + o0 + 8)*NTOT + n_base;
                float2 v0 = { acc[mi][nj][0] + bv0, acc[mi][nj][1] + bv0 };
                float2 v1 = { acc[mi][nj][2] + bv1, acc[mi][nj][3] + bv1 };
                *(float2*)(y0 + col) = v0;
                *(float2*)(y1 + col) = v1;
            }
        }
    }
}

// ================= attention (fp32 f32x2 math; q direct from gmem; k/v fp32 smem) =======
__global__ __launch_bounds__(64) void attn_kernel(const float* __restrict__ rpb) {
    __shared__ float ks[2048];
    __shared__ float vs[2048];
    __shared__ float rpb_s[225];

    int head = blockIdx.x, d = blockIdx.y, b = blockIdx.z;
    int t = threadIdx.x;

    const __half* base = g_qkv + ((size_t)(b*O3 + head*HDIM))*NTOT + d*64;
    for (int i = t; i < 2048; i += 64) {
        int hd = i >> 6, n = i & 63;
        ks[i] = __half2float(base[(size_t)(256 + hd)*NTOT + n]);
        vs[i] = __half2float(base[(size_t)(512 + hd)*NTOT + n]);
    }
    for (int i = t; i < 225; i += 64) rpb_s[i] = rpb[i*HEADS + head];

    const int n = t, hn = n >> 3, wn = n & 7;
    const float scale = 0.17677669529663687f;

    // q: coalesced direct gmem loads (thread n reads its own column)
    float qr[32];
    #pragma unroll
    for (int hd = 0; hd < 32; ++hd) qr[hd] = __half2float(base[(size_t)hd*NTOT + n]);
    __syncthreads();

    u64t acc2[32];
    #pragma unroll
    for (int j = 0; j < 32; ++j) acc2[j] = 0ull;
    #pragma unroll
    for (int hd = 0; hd < 32; ++hd) {
        u64t qd = pk2(qr[hd], qr[hd]);
        const ulonglong2* kp = (const ulonglong2*)&ks[hd*64];
        #pragma unroll
        for (int m4 = 0; m4 < 16; ++m4) {
            ulonglong2 kk = kp[m4];
            fma2(acc2[m4*2],     qd, kk.x);
            fma2(acc2[m4*2 + 1], qd, kk.y);
        }
    }

    float sc[64];
    #pragma unroll
    for (int j = 0; j < 32; ++j) upk2(acc2[j], sc[2*j], sc[2*j + 1]);
    #pragma unroll
    for (int m = 0; m < 64; ++m) {
        int di = hn - (m >> 3) + 7;
        int dj = wn - (m & 7) + 7;
        sc[m] = sc[m]*scale + rpb_s[di*15 + dj];
    }

    float mx = -1e30f;
    #pragma unroll
    for (int m = 0; m < 64; ++m) mx = fmaxf(mx, sc[m]);
    float sum = 0.f;
    #pragma unroll
    for (int m = 0; m < 64; ++m) { sc[m] = __expf(sc[m] - mx); sum += sc[m]; }
    float inv = 1.f / sum;

    #pragma unroll
    for (int j = 0; j < 32; ++j) acc2[j] = pk2(sc[2*j]*inv, sc[2*j + 1]*inv);

    __half* ysl = g_xat + ((size_t)(b*NTOT + d*64 + n))*CC + head*HDIM;
    #pragma unroll
    for (int hd4 = 0; hd4 < 8; ++hd4) {
        float op[4];
        #pragma unroll
        for (int q = 0; q < 4; ++q) {
            int hd = hd4*4 + q;
            u64t o2 = 0ull;
            const ulonglong2* vp = (const ulonglong2*)&vs[hd*64];
            #pragma unroll
            for (int m4 = 0; m4 < 16; ++m4) {
                ulonglong2 vv = vp[m4];
                fma2(o2, acc2[m4*2],     vv.x);
                fma2(o2, acc2[m4*2 + 1], vv.y);
            }
            float lo, hi; upk2(o2, lo, hi);
            op[q] = lo + hi;
        }
        *(__half2*)(ysl + hd4*4)     = __floats2half2_rn(op[0], op[1]);
        *(__half2*)(ysl + hd4*4 + 2) = __floats2half2_rn(op[2], op[3]);
    }
}

// ================= launch =================
extern "C" void kernel_launch(void* const* d_in, const int* in_sizes, int n_in,
                              void* d_out, int out_size) {
    const float* x   = (const float*)d_in[0];
    const float* dw  = (const float*)d_in[1];
    const float* dwb = (const float*)d_in[2];
    const float* qw  = (const float*)d_in[3];
    const float* qb  = (const float*)d_in[4];
    const float* pw  = (const float*)d_in[5];
    const float* pb  = (const float*)d_in[6];
    const float* rpb = (const float*)d_in[7];
    float* out = (float*)d_out;

    bool big = true;
    big &= cudaFuncSetAttribute(conv_mma3, cudaFuncAttributeMaxDynamicSharedMemorySize, CV_SMEM3) == cudaSuccess;
    big &= cudaFuncSetAttribute(gemm_mma3<O3,0>, cudaFuncAttributeMaxDynamicSharedMemorySize, G3_SMEM) == cudaSuccess;
    big &= cudaFuncSetAttribute(gemm_mma3<CC,1>, cudaFuncAttributeMaxDynamicSharedMemorySize, G3_SMEM) == cudaSuccess;

    prep_weights<<<(9*CC*CC + 255)/256, 256>>>(dw, qw, pw);
    pad_transpose<<<dim3(DD, BB), 256>>>(x);
    if (big) {
        conv_mma3<<<dim3(2, 50, BB), 256, CV_SMEM3>>>(dwb);
        gemm_mma3<O3,0><<<dim3(6, 50, BB), 256, G3_SMEM>>>(qb, nullptr);
    } else {
        conv_mma<32><<<dim3(2, 50, BB), 256, TC<32>::SMEMB>>>(dwb);
        gemm_mma<O3,0,32><<<dim3(6, 50, BB), 256, TC<32>::SMEMB>>>(qb, nullptr);
    }
    attn_kernel<<<dim3(HEADS, DD, BB), 64>>>(rpb);
    if (big) {
        gemm_mma3<CC,1><<<dim3(2, 50, BB), 256, G3_SMEM>>>(pb, out);
    } else {
        gemm_mma<CC,1,32><<<dim3(2, 50, BB), 256, TC<32>::SMEMB>>>(pb, out);
    }
}